// round 4
// baseline (speedup 1.0000x reference)
#include <cuda_runtime.h>
#include <cuda_bf16.h>
#include <cstdint>

// LNLieBracketChannelMix via mma.sync bf16-split (fp32 = hi+lo bf16, 3 HMMA/product).
// out[b,g,k,n] = x[b,g,k,n] + cross(M2@d2, M1@d1)[k],  d_i = W_i @ x[b] over f.
// R4: 8 warps (warps 0-3 -> D1, warps 4-7 -> D2), split-term-major MMA order
//     (12 independent accumulators between reuses), 2 CTAs/SM.

#define B_    8
#define F_    256
#define NDIM  4096
#define COLS  12288         // 3*NDIM
#define GT    64            // g per CTA
#define NT    32            // n per CTA
#define CT    96            // 3 k-slices * NT
#define KC    32            // f chunk
#define NCH   8
#define THREADS 256

#define A_STRIDE 80         // bytes per A row (32 bf16 = 64B + 16B pad)
#define B_STRIDE 208        // bytes per B row (96 bf16 = 192B + 16B pad)
#define A_PART   (GT * A_STRIDE)        // 5120
#define B_PART   (KC * B_STRIDE)        // 6656
#define BH_OFF   (4 * A_PART)           // 20480
#define BL_OFF   (BH_OFF + B_PART)      // 27136
#define STAGE    (BH_OFF + 2 * B_PART)  // 33792
#define SMEM_TOTAL (2 * STAGE)          // 67584 (epilogue needs 49152, reused)

static __device__ __forceinline__ uint32_t s2u(const void* p) {
    uint32_t a;
    asm("{ .reg .u64 t; cvta.to.shared.u64 t, %1; cvt.u32.u64 %0, t; }" : "=r"(a) : "l"(p));
    return a;
}
static __device__ __forceinline__ void lm4(uint32_t* r, uint32_t a) {
    asm volatile("ldmatrix.sync.aligned.m8n8.x4.shared.b16 {%0,%1,%2,%3}, [%4];"
        : "=r"(r[0]), "=r"(r[1]), "=r"(r[2]), "=r"(r[3]) : "r"(a));
}
static __device__ __forceinline__ void lm4t(uint32_t* r, uint32_t a) {
    asm volatile("ldmatrix.sync.aligned.m8n8.x4.trans.shared.b16 {%0,%1,%2,%3}, [%4];"
        : "=r"(r[0]), "=r"(r[1]), "=r"(r[2]), "=r"(r[3]) : "r"(a));
}
static __device__ __forceinline__ void mma(float* d, const uint32_t* a, uint32_t b0, uint32_t b1) {
    asm volatile(
        "mma.sync.aligned.m16n8k16.row.col.f32.bf16.bf16.f32 "
        "{%0,%1,%2,%3}, {%4,%5,%6,%7}, {%8,%9}, {%0,%1,%2,%3};"
        : "+f"(d[0]), "+f"(d[1]), "+f"(d[2]), "+f"(d[3])
        : "r"(a[0]), "r"(a[1]), "r"(a[2]), "r"(a[3]), "r"(b0), "r"(b1));
}
static __device__ __forceinline__ uint32_t pk2(__nv_bfloat16 a, __nv_bfloat16 b) {
    __nv_bfloat162 t = __halves2bfloat162(a, b);
    return *reinterpret_cast<uint32_t*>(&t);
}
static __device__ __forceinline__ void split4(float4 w, uint2& hv, uint2& lv) {
    __nv_bfloat16 hx = __float2bfloat16(w.x), hy = __float2bfloat16(w.y);
    __nv_bfloat16 hz = __float2bfloat16(w.z), hw = __float2bfloat16(w.w);
    hv.x = pk2(hx, hy); hv.y = pk2(hz, hw);
    lv.x = pk2(__float2bfloat16(w.x - __bfloat162float(hx)),
               __float2bfloat16(w.y - __bfloat162float(hy)));
    lv.y = pk2(__float2bfloat16(w.z - __bfloat162float(hz)),
               __float2bfloat16(w.w - __bfloat162float(hw)));
}

__global__ __launch_bounds__(THREADS, 2)
void lnlb_mma_kernel(const float* __restrict__ x,
                     const float* __restrict__ M1,
                     const float* __restrict__ M2,
                     const float* __restrict__ W1,
                     const float* __restrict__ W2,
                     float* __restrict__ out)
{
    extern __shared__ char smem[];
    const uint32_t sb = s2u(smem);

    const int tid = threadIdx.x;
    const int warp = tid >> 5, lane = tid & 31;
    const int n0 = blockIdx.x * NT;
    const int g0 = blockIdx.y * GT;
    const int b  = blockIdx.z;
    const float* xb = x + (size_t)b * F_ * COLS;

    const int mat = warp >> 2;           // 0 -> W1/D1, 1 -> W2/D2
    const int q   = warp & 3;
    const int wg  = (q >> 1) * 32;       // warp g offset (0/32)
    const int wc  = (q & 1) * 48;        // warp col offset (0/48)

    float acc[2][6][4];
    #pragma unroll
    for (int m = 0; m < 2; m++)
        #pragma unroll
        for (int t = 0; t < 6; t++)
            #pragma unroll
            for (int j = 0; j < 4; j++) acc[m][t][j] = 0.f;

    // ldmatrix lane offsets
    const int lrow = lane & 15;
    const uint32_t lhA = (lane & 16) ? 16u : 0u;
    const uint32_t lhB = (lane & 16) ? 8u  : 0u;
    uint32_t aoff[2], boff[3];
    #pragma unroll
    for (int m = 0; m < 2; m++) aoff[m] = (uint32_t)((wg + 16 * m + lrow) * A_STRIDE) + lhA;
    #pragma unroll
    for (int t = 0; t < 3; t++) boff[t] = (uint32_t)(lrow * B_STRIDE + (wc + t * 16 + lhB) * 2);

    const uint32_t aBaseH = (uint32_t)(mat * 2 * A_PART);   // this warp's W hi tile
    const uint32_t aBaseL = aBaseH + (uint32_t)A_PART;      // lo tile

    // ---- staging: chunk c into buffer buf ----
    auto stage = [&](int c, char* buf) {
        const int f0 = c * KC;
        // A: W1,W2 chunk [64 g x 32 f] -> 4 bf16 tiles (w1h,w1l,w2h,w2l)
        #pragma unroll
        for (int i = tid; i < 1024; i += THREADS) {
            int w = i >> 9, r = i & 511, g = r >> 3, fq = r & 7;
            const float* W = w ? W2 : W1;
            float4 v = *(const float4*)(W + (g0 + g) * F_ + f0 + fq * 4);
            uint2 hv, lv; split4(v, hv, lv);
            char* dst = buf + w * 2 * A_PART + g * A_STRIDE + fq * 8;
            *(uint2*)dst = hv;
            *(uint2*)(dst + A_PART) = lv;
        }
        // B: x chunk [32 f x 96 cols] -> hi/lo
        #pragma unroll
        for (int i = tid; i < 768; i += THREADS) {
            int f = i / 24, cq = i % 24;
            const float* src = xb + (size_t)(f0 + f) * COLS + (cq >> 3) * NDIM + n0 + (cq & 7) * 4;
            float4 v = *(const float4*)src;
            uint2 hv, lv; split4(v, hv, lv);
            uint32_t off = (uint32_t)(f * B_STRIDE + cq * 8);
            *(uint2*)(buf + BH_OFF + off) = hv;
            *(uint2*)(buf + BL_OFF + off) = lv;
        }
    };

    stage(0, smem);
    __syncthreads();

    for (int c = 0; c < NCH; ++c) {
        if (c + 1 < NCH) stage(c + 1, smem + ((c + 1) & 1) * STAGE);

        const uint32_t bu = sb + (uint32_t)((c & 1) * STAGE);
        #pragma unroll
        for (int ks2 = 0; ks2 < 2; ++ks2) {
            const uint32_t ksA = ks2 * 32;              // 16 bf16 = 32 B
            const uint32_t ksB = ks2 * 16 * B_STRIDE;   // 16 rows

            uint32_t Ah[2][4], Al[2][4];
            #pragma unroll
            for (int m = 0; m < 2; m++) {
                lm4(Ah[m], bu + aBaseH + aoff[m] + ksA);
                lm4(Al[m], bu + aBaseL + aoff[m] + ksA);
            }
            uint32_t BH[3][4], BL[3][4];
            #pragma unroll
            for (int t = 0; t < 3; t++) {
                lm4t(BH[t], bu + BH_OFF + boff[t] + ksB);
                lm4t(BL[t], bu + BL_OFF + boff[t] + ksB);
            }
            // split-term-major: 12 independent accumulators per term group
            #pragma unroll
            for (int m = 0; m < 2; m++)
                #pragma unroll
                for (int t = 0; t < 3; t++) {
                    mma(acc[m][2*t],   Ah[m], BH[t][0], BH[t][1]);
                    mma(acc[m][2*t+1], Ah[m], BH[t][2], BH[t][3]);
                }
            #pragma unroll
            for (int m = 0; m < 2; m++)
                #pragma unroll
                for (int t = 0; t < 3; t++) {
                    mma(acc[m][2*t],   Ah[m], BL[t][0], BL[t][1]);
                    mma(acc[m][2*t+1], Ah[m], BL[t][2], BL[t][3]);
                }
            #pragma unroll
            for (int m = 0; m < 2; m++)
                #pragma unroll
                for (int t = 0; t < 3; t++) {
                    mma(acc[m][2*t],   Al[m], BH[t][0], BH[t][1]);
                    mma(acc[m][2*t+1], Al[m], BH[t][2], BH[t][3]);
                }
        }
        __syncthreads();
    }

    // ---- dump accumulators to smem (reuse stage buffers) ----
    float* D1s = (float*)smem;
    float* D2s = D1s + GT * CT;
    {
        float* Ds = mat ? D2s : D1s;
        const int dr = wg + (lane >> 2);
        const int dc = wc + (lane & 3) * 2;
        #pragma unroll
        for (int m = 0; m < 2; m++)
            #pragma unroll
            for (int t = 0; t < 6; t++) {
                int r0 = dr + 16 * m, cc = dc + t * 8;
                Ds[r0 * CT + cc]         = acc[m][t][0];
                Ds[r0 * CT + cc + 1]     = acc[m][t][1];
                Ds[(r0 + 8) * CT + cc]   = acc[m][t][2];
                Ds[(r0 + 8) * CT + cc+1] = acc[m][t][3];
            }
    }
    __syncthreads();

    // ---- epilogue: rotate by M1/M2, cross, add x ----
    float m1[9], m2[9];
    #pragma unroll
    for (int i = 0; i < 9; i++) { m1[i] = M1[i]; m2[i] = M2[i]; }

    #pragma unroll
    for (int p = tid; p < GT * NT; p += THREADS) {
        int g = p >> 5, nn = p & 31;
        float e10 = D1s[g * CT + 0 * NT + nn];
        float e11 = D1s[g * CT + 1 * NT + nn];
        float e12 = D1s[g * CT + 2 * NT + nn];
        float e20 = D2s[g * CT + 0 * NT + nn];
        float e21 = D2s[g * CT + 1 * NT + nn];
        float e22 = D2s[g * CT + 2 * NT + nn];
        float q0 = fmaf(m1[0], e10, fmaf(m1[1], e11, m1[2] * e12));
        float q1 = fmaf(m1[3], e10, fmaf(m1[4], e11, m1[5] * e12));
        float q2 = fmaf(m1[6], e10, fmaf(m1[7], e11, m1[8] * e12));
        float r0 = fmaf(m2[0], e20, fmaf(m2[1], e21, m2[2] * e22));
        float r1 = fmaf(m2[3], e20, fmaf(m2[4], e21, m2[5] * e22));
        float r2 = fmaf(m2[6], e20, fmaf(m2[7], e21, m2[8] * e22));
        float v0 = r1 * q2 - r2 * q1;   // cross(M2 d2, M1 d1)
        float v1 = r2 * q0 - r0 * q2;
        float v2 = r0 * q1 - r1 * q0;

        size_t base = ((size_t)(b * F_ + g0 + g) * 3) * NDIM + n0 + nn;
        out[base]            = x[base]            + v0;
        out[base + NDIM]     = x[base + NDIM]     + v1;
        out[base + 2 * NDIM] = x[base + 2 * NDIM] + v2;
    }
}

extern "C" void kernel_launch(void* const* d_in, const int* in_sizes, int n_in,
                              void* d_out, int out_size)
{
    const float* x  = (const float*)d_in[0];
    const float* M1 = (const float*)d_in[1];
    const float* M2 = (const float*)d_in[2];
    const float* W1 = (const float*)d_in[3];
    const float* W2 = (const float*)d_in[4];
    float* out = (float*)d_out;

    cudaFuncSetAttribute(lnlb_mma_kernel, cudaFuncAttributeMaxDynamicSharedMemorySize, SMEM_TOTAL);
    dim3 grid(NDIM / NT, F_ / GT, B_);   // (128, 4, 8)
    lnlb_mma_kernel<<<grid, THREADS, SMEM_TOTAL>>>(x, M1, M2, W1, W2, out);
}